// round 7
// baseline (speedup 1.0000x reference)
#include <cuda_runtime.h>
#include <cstdint>

#define T 256            // threads per block = rows per block
#define RPB 256
#define NCOLS 14
#define IN_BYTES  (RPB * NCOLS * 4)   // 14336 B per full block
#define OUT_BYTES (RPB * 3 * 4)       //  3072 B per full block

__device__ __forceinline__ uint32_t smem_u32(const void* p) {
    uint32_t a;
    asm("{ .reg .u64 t; cvta.to.shared.u64 t, %1; cvt.u32.u64 %0, t; }" : "=r"(a) : "l"(p));
    return a;
}

__global__ __launch_bounds__(T, 8)
void indicator_kernel(const float* __restrict__ in, float* __restrict__ out,
                      int nfull, int n) {
    __shared__ alignas(128) float s_in[RPB * NCOLS];   // 14336 B
    __shared__ alignas(128) float s_out[RPB * 3];      //  3072 B
    __shared__ alignas(8)  uint64_t mbar;

    const int tid = threadIdx.x;
    const int bid = blockIdx.x;
    const bool full = bid < nfull;
    const uint32_t in_bytes  = full ? IN_BYTES  : (uint32_t)(n - nfull * RPB) * NCOLS * 4;
    const uint32_t out_bytes = full ? OUT_BYTES : (uint32_t)(n - nfull * RPB) * 3 * 4;

    const uint32_t mb  = smem_u32(&mbar);
    const uint32_t sin = smem_u32(s_in);

    if (tid == 0) {
        asm volatile("mbarrier.init.shared.b64 [%0], 1;" :: "r"(mb) : "memory");
    }
    __syncthreads();

    if (tid == 0) {
        asm volatile("mbarrier.arrive.expect_tx.shared.b64 _, [%0], %1;"
                     :: "r"(mb), "r"(in_bytes) : "memory");
        const char* src = (const char*)in + (size_t)bid * IN_BYTES;
        asm volatile(
            "cp.async.bulk.shared::cta.global.mbarrier::complete_tx::bytes [%0], [%1], %2, [%3];"
            :: "r"(sin), "l"(src), "r"(in_bytes), "r"(mb) : "memory");
    }

    // wait for bulk load (phase 0)
    {
        uint32_t done = 0;
        while (!done) {
            asm volatile(
                "{\n\t.reg .pred p;\n\t"
                "mbarrier.try_wait.parity.acquire.cta.shared::cta.b64 p, [%1], 0;\n\t"
                "selp.b32 %0, 1, 0, p;\n\t}"
                : "=r"(done) : "r"(mb) : "memory");
        }
    }

    // ---- per-row compute: one row per thread ----
    const int row = bid * RPB + tid;
    if (row < n) {
        const float*  r  = &s_in[tid * NCOLS];
        const float2* r2 = (const float2*)r;          // 56t bytes -> 8B aligned
        const float2 oc = r2[0];                      // cols 0,1
        const float  lw = r[5];
        const float  uw = r[6];
        const float2 ms = r2[4];                      // cols 8,9
        const float2 sb_ = r2[5];                     // cols 10,11
        const float2 mb2 = r2[6];                     // cols 12,13
        const float ha_open  = oc.x;
        const float ha_close = oc.y;
        const float ma   = ms.x;
        const float srsi = ms.y;
        const float ssig = sb_.x;
        const float bu   = sb_.y;
        const float bm   = mb2.x;
        const float bl   = mb2.y;

        const bool  bullish = ha_close > ha_open;
        const bool  bearish = ha_close < ha_open;
        const float body    = fabsf(ha_close - ha_open);
        const bool  sb = bullish && (body > 0.5f) && (uw < 1e-6f);  // strong_bullish
        const bool  sB = bearish && (body > 0.5f) && (lw < 1e-6f);  // strong_bearish

        const float ha2 = sb ? 0.8f : 0.0f;
        const float ha0 = sB ? 0.8f : 0.0f;

        const float width = (bu - bl) / bm;
        const float pp    = (ha_close - bl) / (bu - bl);
        // structurally false, kept for exact fidelity (NaN behavior identical):
        const bool  sqexp = (width < 0.1f) && (width > 0.2f);
        const float sqf   = sqexp ? 0.9f : 0.0f;

        const bool pp_lo = pp < 0.2f;
        const bool pp_hi = pp > 0.8f;
        const float bb2 = (pp_lo ? 0.8f : 0.0f) + sqf;
        const float bb0 = (pp_hi ? 0.8f : 0.0f) + sqf;

        const float st2 = (srsi < 0.2f) ? 0.8f : 0.0f;
        const float st0 = (srsi > 0.8f) ? 0.8f : 0.0f;

        const bool  ma_up = ma > 0.1f;
        const bool  ma_dn = ma < -0.1f;
        const float ma2 = ma_up ? 0.7f : 0.0f;
        const float ma0 = ma_dn ? 0.7f : 0.0f;

        const bool st_dn = ssig < -0.1f;
        const bool st_up = ssig > 0.1f;

        // OR of all 3-of-4 conjunctions == majority(>=3 of 4)
        const bool long_sig  = ((int)sb + (int)ma_up + (int)st_dn + (int)pp_lo) >= 3;
        const bool short_sig = ((int)sB + (int)ma_dn + (int)st_up + (int)pp_hi) >= 3;

        const float hms2 = long_sig  ? 0.9f : 0.0f;
        const float hms0 = short_sig ? 0.9f : 0.0f;

        const float col0 = ha0 + ma0 + st0 + bb0 + 2.0f * hms0;
        const float col2 = ha2 + ma2 + st2 + bb2 + 2.0f * hms2;
        const float col1 = 1.5f;

        const float m  = fmaxf(fmaxf(col0, col2), col1);
        const float e0 = __expf(col0 - m);
        const float e1 = __expf(col1 - m);
        const float e2 = __expf(col2 - m);
        const float inv = 1.0f / (e0 + e1 + e2);

        s_out[tid * 3 + 0] = e0 * inv;
        s_out[tid * 3 + 1] = e1 * inv;
        s_out[tid * 3 + 2] = e2 * inv;
    }
    __syncthreads();

    // ---- bulk-async store: smem -> gmem ----
    if (tid == 0) {
        asm volatile("fence.proxy.async.shared::cta;" ::: "memory");
        char* dst = (char*)out + (size_t)bid * OUT_BYTES;
        const uint32_t sout = smem_u32(s_out);
        asm volatile(
            "cp.async.bulk.global.shared::cta.bulk_group [%0], [%1], %2;"
            :: "l"(dst), "r"(sout), "r"(out_bytes) : "memory");
        asm volatile("cp.async.bulk.commit_group;" ::: "memory");
        asm volatile("cp.async.bulk.wait_group 0;" ::: "memory");
    }
}

extern "C" void kernel_launch(void* const* d_in, const int* in_sizes, int n_in,
                              void* d_out, int out_size) {
    const float* in = (const float*)d_in[0];
    float* out = (float*)d_out;
    const int n = in_sizes[0] / NCOLS;       // 2,000,000 rows
    const int grid  = (n + RPB - 1) / RPB;   // 7813 blocks
    const int nfull = n / RPB;               // 7812 full blocks
    indicator_kernel<<<grid, T>>>(in, out, nfull, n);
}